// round 7
// baseline (speedup 1.0000x reference)
#include <cuda_runtime.h>
#include <cuda_bf16.h>
#include <cstdint>

#define NROWS  65536
#define DDIM   256
#define KCODES 4096
#define QTZ_BETA 0.25
#define BM 128
#define BNC 128                 // codes per chunk
#define NCHUNK (KCODES / BNC)   // 32
#define KD 128                  // d per stage
#define NIT (NCHUNK * 2)        // 64
#define CAP 64

// -------- device scratch --------
__device__ __nv_bfloat16 g_zh[NROWS][DDIM];    // 32MB
__device__ __nv_bfloat16 g_cbh[KCODES][DDIM];  // 2MB
__device__ float  g_znorm[NROWS];
__device__ float  g_cnorm[KCODES];
__device__ float  g_maxcn;
__device__ double g_loss;
__device__ int    g_ccount[NROWS];
__device__ int    g_cand[NROWS][CAP];

// -------- smem map (bytes) --------
// 3 stages of [z(32KB) | c(32KB)], then min/cnt/margin/cand
#define STGP 65536
#define OFF_MIN  (3 * STGP)             // 196608 (128 u32)
#define OFF_CNT  (OFF_MIN + 512)
#define OFF_MR   (OFF_CNT + 512)
#define OFF_CAND (OFF_MR + 512)         // 198144: 128*64*4 = 32768
#define SMEM_TOTAL (OFF_CAND + 32768)   // 230912

// ---------------- PTX helpers ----------------
__device__ __forceinline__ uint32_t smem_u32(const void* p) {
    uint32_t a;
    asm("{ .reg .u64 t; cvta.to.shared.u64 t, %1; cvt.u32.u64 %0, t; }" : "=r"(a) : "l"(p));
    return a;
}
__device__ __forceinline__ void cp_async16(uint32_t dst, const void* src) {
    asm volatile("cp.async.cg.shared.global [%0], [%1], 16;" :: "r"(dst), "l"(src) : "memory");
}
#define CP_COMMIT() asm volatile("cp.async.commit_group;" ::: "memory")
#define CP_WAIT(n)  asm volatile("cp.async.wait_group %0;" :: "n"(n) : "memory")

__device__ __forceinline__ void ldsm4(uint32_t* r, uint32_t addr) {
    asm volatile("ldmatrix.sync.aligned.m8n8.x4.shared.b16 {%0,%1,%2,%3}, [%4];"
                 : "=r"(r[0]), "=r"(r[1]), "=r"(r[2]), "=r"(r[3]) : "r"(addr));
}
__device__ __forceinline__ void mma_bf16(float* c, const uint32_t* a,
                                         uint32_t b0, uint32_t b1) {
    asm volatile(
        "mma.sync.aligned.m16n8k16.row.col.f32.bf16.bf16.f32 "
        "{%0,%1,%2,%3}, {%4,%5,%6,%7}, {%8,%9}, {%0,%1,%2,%3};"
        : "+f"(c[0]), "+f"(c[1]), "+f"(c[2]), "+f"(c[3])
        : "r"(a[0]), "r"(a[1]), "r"(a[2]), "r"(a[3]), "r"(b0), "r"(b1));
}

// ordered-uint keys for float atomicMin
__device__ __forceinline__ uint32_t fkey(float f) {
    uint32_t u = __float_as_uint(f);
    return (u & 0x80000000u) ? ~u : (u | 0x80000000u);
}
__device__ __forceinline__ float funkey(uint32_t k) {
    return __uint_as_float((k & 0x80000000u) ? (k & 0x7fffffffu) : ~k);
}

// ---------------- init ----------------
__global__ void init_kernel() { g_loss = 0.0; g_maxcn = 0.f; }

// ---------------- prep: bf16 round + norms ----------------
__device__ __forceinline__ float prep_row(const float* __restrict__ src, int row,
                                          __nv_bfloat16 (*dst)[DDIM]) {
    int lane = threadIdx.x & 31;
    const float4* zp = (const float4*)(src + (size_t)row * DDIM) + lane * 2;
    float4 a = zp[0], b = zp[1];
    float v[8] = {a.x, a.y, a.z, a.w, b.x, b.y, b.z, b.w};
    float ns = 0.f;
    uint32_t p[4];
    #pragma unroll
    for (int j = 0; j < 4; j++) {
        float x0 = v[2 * j], x1 = v[2 * j + 1];
        ns += x0 * x0 + x1 * x1;
        __nv_bfloat162 h2 = __float22bfloat162_rn(make_float2(x0, x1));
        p[j] = *reinterpret_cast<uint32_t*>(&h2);
    }
    ((uint4*)dst[row])[lane] = make_uint4(p[0], p[1], p[2], p[3]);
    #pragma unroll
    for (int o = 16; o > 0; o >>= 1) ns += __shfl_down_sync(0xffffffffu, ns, o);
    return ns;
}
__global__ void prep_z(const float* __restrict__ z) {
    int row = blockIdx.x * 8 + (threadIdx.x >> 5);
    float ns = prep_row(z, row, g_zh);
    if ((threadIdx.x & 31) == 0) g_znorm[row] = ns;
}
__global__ void prep_cb(const float* __restrict__ cb) {
    int row = blockIdx.x * 8 + (threadIdx.x >> 5);
    float ns = prep_row(cb, row, g_cbh);
    if ((threadIdx.x & 31) == 0) {
        g_cnorm[row] = ns;
        atomicMax((int*)&g_maxcn, __float_as_int(ns));
    }
}

// ---------------- pass1 stage loader (256 threads) ----------------
__device__ __forceinline__ void load_stage(uint32_t sb, int it, int rowBase, int tid) {
    const uint32_t stg = sb + (uint32_t)(it % 3) * STGP;
    const int dOff = (it & 1) * KD;
    const int chunk = it >> 1;
    #pragma unroll
    for (int j = 0; j < 8; j++) {
        int q = j * 256 + tid;          // 0..2047
        int r = q >> 4, c = q & 15;
        cp_async16(stg + r * 256 + (((c ^ (r & 7))) << 4),
                   &g_zh[rowBase + r][dOff + c * 8]);
    }
    const int codeBase = chunk * BNC;
    #pragma unroll
    for (int j = 0; j < 8; j++) {
        int q = j * 256 + tid;
        int r = q >> 4, c = q & 15;
        cp_async16(stg + 32768 + r * 256 + (((c ^ (r & 7))) << 4),
                   &g_cbh[codeBase + r][dOff + c * 8]);
    }
}

// ---------------- pass1: approx GEMM + candidate collection ----------------
// 8 warps, warp tile 32 rows x 64 codes; explicit frag double-buffering.
__global__ __launch_bounds__(256, 1)
void vq_approx() {
    extern __shared__ char smem[];
    const uint32_t sb = smem_u32(smem);
    const int tid = threadIdx.x;
    const uint32_t lane = tid & 31;
    const int wid = tid >> 5;
    const int mW = wid & 3;        // 4-way M split (32 rows each)
    const int nW = wid >> 2;       // 2-way N split (64 codes each)
    const int rowBase = blockIdx.x * BM;

    uint32_t* sMin  = (uint32_t*)(smem + OFF_MIN);
    int*      sCnt  = (int*)(smem + OFF_CNT);
    float*    sMr   = (float*)(smem + OFF_MR);
    int*      sCand = (int*)(smem + OFF_CAND);

    if (tid < BM) {
        sMin[tid] = 0xFFFFFFFFu;
        sCnt[tid] = 0;
        // rigorous bf16-RN bound: 2^-7 |z||c| = 0.0078 — use 0.0098 + 0.1 abs
        sMr[tid]  = 0.0098f * sqrtf(g_znorm[rowBase + tid]) * sqrtf(g_maxcn) + 0.1f;
    }

    const uint32_t rowAoff = ((uint32_t)(mW * 32) + (lane & 15)) * 256;
    const uint32_t nRowoff = ((uint32_t)(nW * 64) + (lane & 7) + ((lane >> 4) << 3)) * 256;
    const uint32_t swz = lane & 7;
    const uint32_t kHA = lane >> 4;
    const uint32_t kHB = (lane >> 3) & 1;

    float acc[2][8][4];
    #pragma unroll
    for (int mt = 0; mt < 2; mt++)
        #pragma unroll
        for (int nt = 0; nt < 8; nt++)
            #pragma unroll
            for (int e = 0; e < 4; e++) acc[mt][nt][e] = 0.f;

    load_stage(sb, 0, rowBase, tid);
    CP_COMMIT();
    load_stage(sb, 1, rowBase, tid);
    CP_COMMIT();

    #pragma unroll 1
    for (int it = 0; it < NIT; it++) {
        // my copies for stage it complete...
        CP_WAIT(1);
        // ...barrier makes them visible to all warps; it also retires all
        // reads of stage it-1, so buffer (it+2)%3 is safe to refill below.
        __syncthreads();
        if (it + 2 < NIT) load_stage(sb, it + 2, rowBase, tid);
        CP_COMMIT();                   // keep group count aligned near the end

        const uint32_t stg = sb + (uint32_t)(it % 3) * STGP;
        const uint32_t aB = stg + rowAoff;
        const uint32_t bB = stg + 32768 + nRowoff;

        // fragment double buffer: prefetch kk+1 while issuing kk's 16 HMMAs
        uint32_t af[2][2][4], bf[2][4][4];
        {
            const uint32_t aCol0 = (kHA ^ swz) << 4;
            const uint32_t bCol0 = (kHB ^ swz) << 4;
            ldsm4(af[0][0], aB + 0 * 4096 + aCol0);
            ldsm4(af[0][1], aB + 1 * 4096 + aCol0);
            #pragma unroll
            for (int i = 0; i < 4; i++) ldsm4(bf[0][i], bB + i * 4096 + bCol0);
        }
        #pragma unroll
        for (int kk = 0; kk < 8; kk++) {
            const int cur = kk & 1, nxt = cur ^ 1;
            if (kk < 7) {
                const uint32_t aCol = ((2u * (kk + 1) + kHA) ^ swz) << 4;
                const uint32_t bCol = ((2u * (kk + 1) + kHB) ^ swz) << 4;
                ldsm4(af[nxt][0], aB + 0 * 4096 + aCol);
                ldsm4(af[nxt][1], aB + 1 * 4096 + aCol);
                #pragma unroll
                for (int i = 0; i < 4; i++) ldsm4(bf[nxt][i], bB + i * 4096 + bCol);
            }
            #pragma unroll
            for (int mt = 0; mt < 2; mt++)
                #pragma unroll
                for (int i = 0; i < 4; i++) {
                    mma_bf16(acc[mt][2 * i],     af[cur][mt], bf[cur][i][0], bf[cur][i][1]);
                    mma_bf16(acc[mt][2 * i + 1], af[cur][mt], bf[cur][i][2], bf[cur][i][3]);
                }
        }

        if (it & 1) {
            // chunk epilogue: e = ||c||^2 - 2 z.c; stale-min threshold, no barrier
            const int chunk = it >> 1;
            const int jb = chunk * BNC + nW * 64 + (int)(lane & 3) * 2;

            float rmin[4];
            #pragma unroll
            for (int q = 0; q < 4; q++) rmin[q] = 3.4e38f;

            #pragma unroll
            for (int nt = 0; nt < 8; nt++) {
                const float2 cn = __ldg((const float2*)(g_cnorm + jb + nt * 8));
                #pragma unroll
                for (int mt = 0; mt < 2; mt++) {
                    float e0 = fmaf(-2.f, acc[mt][nt][0], cn.x);
                    float e1 = fmaf(-2.f, acc[mt][nt][1], cn.y);
                    float e2 = fmaf(-2.f, acc[mt][nt][2], cn.x);
                    float e3 = fmaf(-2.f, acc[mt][nt][3], cn.y);
                    acc[mt][nt][0] = e0; acc[mt][nt][1] = e1;
                    acc[mt][nt][2] = e2; acc[mt][nt][3] = e3;
                    rmin[2 * mt]     = fminf(rmin[2 * mt],     fminf(e0, e1));
                    rmin[2 * mt + 1] = fminf(rmin[2 * mt + 1], fminf(e2, e3));
                }
            }
            // reduce over the 4 lanes sharing each row (lane&3 group)
            #pragma unroll
            for (int q = 0; q < 4; q++) {
                rmin[q] = fminf(rmin[q], __shfl_xor_sync(0xffffffffu, rmin[q], 1));
                rmin[q] = fminf(rmin[q], __shfl_xor_sync(0xffffffffu, rmin[q], 2));
            }
            #pragma unroll
            for (int q = 0; q < 4; q++) {
                const int mt = q >> 1, h = q & 1;
                const int r = mW * 32 + mt * 16 + (int)(lane >> 2) + h * 8;
                if ((lane & 3) == 0) atomicMin(&sMin[r], fkey(rmin[q]));
                const float gm = funkey(sMin[r]);         // stale-safe
                const float th = fminf(gm, rmin[q]) + sMr[r];
                #pragma unroll
                for (int nt = 0; nt < 8; nt++) {
                    const float ev0 = acc[mt][nt][2 * h];
                    const float ev1 = acc[mt][nt][2 * h + 1];
                    if (ev0 <= th) {
                        int p = atomicAdd(&sCnt[r], 1);
                        if (p < CAP) sCand[r * CAP + p] = jb + nt * 8;
                    }
                    if (ev1 <= th) {
                        int p = atomicAdd(&sCnt[r], 1);
                        if (p < CAP) sCand[r * CAP + p] = jb + nt * 8 + 1;
                    }
                }
            }
            #pragma unroll
            for (int mt = 0; mt < 2; mt++)
                #pragma unroll
                for (int nt = 0; nt < 8; nt++) {
                    acc[mt][nt][0] = 0.f; acc[mt][nt][1] = 0.f;
                    acc[mt][nt][2] = 0.f; acc[mt][nt][3] = 0.f;
                }
        }
    }

    __syncthreads();
    if (tid < BM) {
        const int cnt = sCnt[tid];
        g_ccount[rowBase + tid] = cnt;
        const int m = cnt < CAP ? cnt : CAP;
        for (int i = 0; i < m; i++)
            g_cand[rowBase + tid][i] = sCand[tid * CAP + i];
    }
}

// ---------------- pass2: exact fp32 rescore + outputs ----------------
__device__ __forceinline__ float cand_dot(const float4& za, const float4& zb,
                                          const float* __restrict__ cb, int id,
                                          int lane) {
    const float4* cp = (const float4*)(cb + (size_t)id * DDIM);
    float4 ca = cp[lane * 2], cc = cp[lane * 2 + 1];
    float d = za.x * ca.x;
    d = fmaf(za.y, ca.y, d); d = fmaf(za.z, ca.z, d); d = fmaf(za.w, ca.w, d);
    d = fmaf(zb.x, cc.x, d); d = fmaf(zb.y, cc.y, d);
    d = fmaf(zb.z, cc.z, d); d = fmaf(zb.w, cc.w, d);
    return d;
}

__global__ __launch_bounds__(256, 1)
void vq_rescore(const float* __restrict__ z, const float* __restrict__ cb,
                float* __restrict__ zq, float* __restrict__ ids_out) {
    __shared__ float sL[8];
    const int w = threadIdx.x >> 5, lane = threadIdx.x & 31;
    const int row = blockIdx.x * 8 + w;

    const float4* zp = (const float4*)(z + (size_t)row * DDIM);
    const float4 za = zp[lane * 2], zb = zp[lane * 2 + 1];
    const float zn = g_znorm[row];
    const int n = g_ccount[row];

    float best = 3.4e38f;
    int bid = 0x7fffffff;
    if (n <= CAP) {
        int i = 0;
        // 2-way unrolled: two concurrent codebook-row loads for MLP
        for (; i + 1 < n; i += 2) {
            const int id0 = g_cand[row][i];
            const int id1 = g_cand[row][i + 1];
            float d0 = cand_dot(za, zb, cb, id0, lane);
            float d1 = cand_dot(za, zb, cb, id1, lane);
            #pragma unroll
            for (int o = 16; o > 0; o >>= 1) {
                d0 += __shfl_xor_sync(0xffffffffu, d0, o);
                d1 += __shfl_xor_sync(0xffffffffu, d1, o);
            }
            float e0 = zn - 2.f * d0 + g_cnorm[id0];
            float e1 = zn - 2.f * d1 + g_cnorm[id1];
            if (e0 < best || (e0 == best && id0 < bid)) { best = e0; bid = id0; }
            if (e1 < best || (e1 == best && id1 < bid)) { best = e1; bid = id1; }
        }
        if (i < n) {
            const int id0 = g_cand[row][i];
            float d0 = cand_dot(za, zb, cb, id0, lane);
            #pragma unroll
            for (int o = 16; o > 0; o >>= 1) d0 += __shfl_xor_sync(0xffffffffu, d0, o);
            float e0 = zn - 2.f * d0 + g_cnorm[id0];
            if (e0 < best || (e0 == best && id0 < bid)) { best = e0; bid = id0; }
        }
    } else {
        for (int id = 0; id < KCODES; id++) {
            float d = cand_dot(za, zb, cb, id, lane);
            #pragma unroll
            for (int o = 16; o > 0; o >>= 1) d += __shfl_xor_sync(0xffffffffu, d, o);
            float e = zn - 2.f * d + g_cnorm[id];
            if (e < best || (e == best && id < bid)) { best = e; bid = id; }
        }
    }

    ids_out[row] = (float)bid;
    const float4* cp = (const float4*)(cb + (size_t)bid * DDIM);
    float4* dst = (float4*)(zq + (size_t)row * DDIM);
    dst[lane * 2]     = cp[lane * 2];
    dst[lane * 2 + 1] = cp[lane * 2 + 1];

    if (lane == 0) sL[w] = best;
    __syncthreads();
    if (threadIdx.x == 0) {
        float s = 0.f;
        #pragma unroll
        for (int i = 0; i < 8; i++) s += sL[i];
        atomicAdd(&g_loss, (double)s);
    }
}

// ---------------- loss finalize ----------------
__global__ void finalize_kernel(float* __restrict__ loss_out) {
    *loss_out = (float)(g_loss * (1.0 + QTZ_BETA) / ((double)NROWS * (double)DDIM));
}

// ---------------- launch ----------------
extern "C" void kernel_launch(void* const* d_in, const int* in_sizes, int n_in,
                              void* d_out, int out_size) {
    const float* z  = (const float*)d_in[0];
    const float* cb = (const float*)d_in[1];
    float* out = (float*)d_out;

    float* zq_out   = out;                          // N*D
    float* loss_out = out + (size_t)NROWS * DDIM;   // 1
    float* ids_out  = loss_out + 1;                 // N

    cudaFuncSetAttribute(vq_approx, cudaFuncAttributeMaxDynamicSharedMemorySize, SMEM_TOTAL);

    init_kernel<<<1, 1>>>();
    prep_z<<<NROWS / 8, 256>>>(z);
    prep_cb<<<KCODES / 8, 256>>>(cb);
    vq_approx<<<NROWS / BM, 256, SMEM_TOTAL>>>();
    vq_rescore<<<NROWS / 8, 256>>>(z, cb, zq_out, ids_out);
    finalize_kernel<<<1, 1>>>(loss_out);
}